// round 13
// baseline (speedup 1.0000x reference)
#include <cuda_runtime.h>
#include <cuda_fp16.h>
#include <cstdint>

#define IN_F   8192
#define OUT_F  8192
#define NTOK   32
#define NCODE  65536
#define GROUPS (IN_F / 8)   // 1024
#define KSPLIT 16
#define KSEG   (IN_F / KSPLIT)   // 512
#define NIT    (KSEG / 64)       // 8
#define NCHUNK 8                 // 8192 = 8 x 1024

// ---------------- device scratch (no allocations allowed) ----------------
__device__ __align__(16) static __half g_cb16[NCODE * 8];        // 1 MB
__device__ __align__(16) static __half g_xh16[NTOK * IN_F];      // 512 KB
__device__ __align__(16) static float g_z[NTOK * OUT_F];         // 1 MB (atomic accum)
__device__ __align__(16) static float g_tmp[NTOK * IN_F];        // 1 MB (FWHT mid)

// ---------------- helpers ----------------
__device__ __forceinline__ uint32_t smem_u32(const void* p) {
    uint32_t a;
    asm("{ .reg .u64 t; cvta.to.shared.u64 t, %1; cvt.u32.u64 %0, t; }"
        : "=r"(a) : "l"(p));
    return a;
}

#define SWZ(off) ((off) ^ (((off) >> 3) & 0x70))

__device__ __forceinline__ void ldmat_x4(uint32_t addr, uint32_t& r0, uint32_t& r1,
                                         uint32_t& r2, uint32_t& r3) {
    asm volatile("ldmatrix.sync.aligned.m8n8.x4.shared.b16 {%0,%1,%2,%3}, [%4];"
                 : "=r"(r0), "=r"(r1), "=r"(r2), "=r"(r3) : "r"(addr));
}
__device__ __forceinline__ void mma16816(float* c, uint32_t a0, uint32_t a1,
                                         uint32_t a2, uint32_t a3,
                                         uint32_t b0, uint32_t b1) {
    asm volatile("mma.sync.aligned.m16n8k16.row.col.f32.f16.f16.f32 "
                 "{%0,%1,%2,%3}, {%4,%5,%6,%7}, {%8,%9}, {%0,%1,%2,%3};"
                 : "+f"(c[0]), "+f"(c[1]), "+f"(c[2]), "+f"(c[3])
                 : "r"(a0), "r"(a1), "r"(a2), "r"(a3), "r"(b0), "r"(b1));
}

// In-smem FWHT over 1024 floats, 256 threads.
__device__ __forceinline__ void fwht1024(float* s, int tid) {
    for (int h = 1; h < 1024; h <<= 1) {
        __syncthreads();
        #pragma unroll
        for (int pp = 0; pp < 2; ++pp) {
            int p = tid + pp * 256;
            int i = 2 * p - (p & (h - 1));
            float a = s[i], b = s[i + h];
            s[i] = a + b;
            s[i + h] = a - b;
        }
    }
    __syncthreads();
}

// 8-point in-register FWHT
__device__ __forceinline__ void fwht8(float* v) {
    #pragma unroll
    for (int h = 1; h < 8; h <<= 1)
        #pragma unroll
        for (int c = 0; c < 8; ++c)
            if (!(c & h)) {
                float a = v[c], b = v[c + h];
                v[c] = a + b;
                v[c + h] = a - b;
            }
}

// ---------------- K_pre: codebook convert + FWHT stage 1 + zero g_z ----------------
// blocks [0,256): codebook fp32->fp16; [256,512): H_1024 of x*SU; [512,576): zero g_z
__global__ void __launch_bounds__(256) k_pre(const float* __restrict__ cb,
                                             const float* __restrict__ x,
                                             const float* __restrict__ SU) {
    if (blockIdx.x >= 512) {
        // zero g_z: 65536 float4 total; 64 blocks x 1024 float4 each, contiguous
        int b4 = (blockIdx.x - 512) * 1024;
        float4 zz = make_float4(0.f, 0.f, 0.f, 0.f);
        #pragma unroll
        for (int pp = 0; pp < 4; ++pp)
            reinterpret_cast<float4*>(g_z)[(size_t)b4 + pp * 256 + threadIdx.x] = zz;
        return;
    }
    if (blockIdx.x < 256) {
        int r = blockIdx.x * 256 + threadIdx.x;
        const float4* p = reinterpret_cast<const float4*>(cb + (size_t)r * 8);
        float4 a = p[0], b = p[1];
        __half2 h0 = __floats2half2_rn(a.x, a.y);
        __half2 h1 = __floats2half2_rn(a.z, a.w);
        __half2 h2 = __floats2half2_rn(b.x, b.y);
        __half2 h3 = __floats2half2_rn(b.z, b.w);
        uint4 v;
        v.x = *reinterpret_cast<unsigned*>(&h0);
        v.y = *reinterpret_cast<unsigned*>(&h1);
        v.z = *reinterpret_cast<unsigned*>(&h2);
        v.w = *reinterpret_cast<unsigned*>(&h3);
        *reinterpret_cast<uint4*>(g_cb16 + (size_t)r * 8) = v;
        return;
    }
    __shared__ float s[1024];
    int bb = blockIdx.x - 256;        // 0..255
    int t = bb >> 3;                  // token
    int ch = bb & 7;                  // chunk
    size_t base = (size_t)t * IN_F + ch * 1024;
    int tid = threadIdx.x;
    {
        float4 xv = reinterpret_cast<const float4*>(x + base)[tid];
        float4 sv = reinterpret_cast<const float4*>(SU + ch * 1024)[tid];
        float4 r;
        r.x = xv.x * sv.x; r.y = xv.y * sv.y;
        r.z = xv.z * sv.z; r.w = xv.w * sv.w;
        reinterpret_cast<float4*>(s)[tid] = r;
    }
    fwht1024(s, tid);
    #pragma unroll
    for (int pp = 0; pp < 4; ++pp) {
        int i = tid + pp * 256;
        g_tmp[base + i] = s[i];
    }
}

// ---------------- K_xh2: FWHT stage 2 (H_8) -> fp16 xh ----------------
__global__ void __launch_bounds__(256) k_xh2() {
    int gid = blockIdx.x * 256 + threadIdx.x;   // 0..32767
    int t = gid >> 10;
    int i = gid & 1023;
    size_t base = (size_t)t * IN_F + i;
    float v[8];
    #pragma unroll
    for (int c = 0; c < 8; ++c) v[c] = g_tmp[base + c * 1024];
    fwht8(v);
    const float sc = 0.011048543456039806f;   // 1/sqrt(8192)
    #pragma unroll
    for (int c = 0; c < 8; ++c)
        g_xh16[base + c * 1024] = __float2half(v[c] * sc);
}

// ---------------- K2: fragment-direct gather + mma.sync, sync-free mainloop ----
// grid (64, 16): x = output tile of 128 rows, y = K segment of 512.
// The FULL B tile for the K segment (32 tokens x 512 k = 32KB) is loaded to
// smem once; after one barrier the 8-iteration mainloop has NO barriers and
// no B logistics: idx prefetch + fragment-direct codebook gathers + LDSM + MMA.
// Epilogue: REDG atomic accumulation into the single g_z buffer.
__global__ void __launch_bounds__(256, 2) k_main(const int* __restrict__ Qidxs) {
    __shared__ __align__(128) unsigned char sm[32768];   // B chunk it at it*4096
    const uint32_t sb = smem_u32(sm);
    const int tid = threadIdx.x;
    const int wid = tid >> 5;
    const int lid = tid & 31;
    const int q  = lid >> 2;      // quad 0..7  (fragment row within m16)
    const int cc = lid & 3;       // pair index 0..3
    const int m0 = blockIdx.x * 128;
    const int kbase = blockIdx.y * KSEG;
    const int gseg  = blockIdx.y * (KSEG / 8);   // group base (64 per seg)

    const __half* __restrict__ xh = g_xh16;
    const char*   __restrict__ cbb = reinterpret_cast<const char*>(g_cb16);

    // ---- load the entire B tile for this K segment (32KB), once ----
    {
        const int r0 = tid >> 3;   // token 0..31
        const int j  = tid & 7;    // 16B column
        uint32_t boff = (uint32_t)((r0 << 7) | (j << 4));
        #pragma unroll
        for (int it = 0; it < NIT; ++it) {
            uint4 bv = *reinterpret_cast<const uint4*>(
                xh + (size_t)r0 * IN_F + kbase + it * 64 + j * 8);
            *reinterpret_cast<uint4*>(sm + it * 4096 + SWZ(boff)) = bv;
        }
    }

    // This lane's Qidxs int4 stream: row = m0 + wid*16 + q + 8*(cc&1),
    // groups [gseg + it*8 + 4*(cc>>1) .. +3]
    const int myrow = m0 + wid * 16 + q + 8 * (cc & 1);
    const int4* qp4 = reinterpret_cast<const int4*>(
        Qidxs + (size_t)myrow * GROUPS + gseg + 4 * (cc >> 1));
    // advance per iter: 8 groups = 2 int4

    float c[4][4];
    #pragma unroll
    for (int g = 0; g < 4; ++g)
        #pragma unroll
        for (int i = 0; i < 4; ++i) c[g][i] = 0.0f;

    // B ldmatrix constants
    const int b_mat  = lid >> 3;
    const int b_nrow = ((b_mat >> 1) * 8) + (lid & 7);
    const int b_kb   = (b_mat & 1) * 16;
    const uint32_t b_base = ((uint32_t)b_nrow << 7) + (uint32_t)b_kb;

    const uint32_t qmask = 0xffffffffu;
    const int qlane = lid & ~3;

// gather the 16 A-fragment regs for one iter from an idx int4
#define GATHER_FRAGS(AF, SIDX)                                                   \
    {                                                                            \
        int comps[4] = {(SIDX).x, (SIDX).y, (SIDX).z, (SIDX).w};                 \
        _Pragma("unroll")                                                        \
        for (int kk = 0; kk < 4; ++kk) {                                         \
            int hb = (kk >> 1) * 2;                                              \
            int i00 = __shfl_sync(qmask, comps[(2 * kk) & 3],     qlane + hb);   \
            int i10 = __shfl_sync(qmask, comps[(2 * kk) & 3],     qlane + hb + 1);\
            int i01 = __shfl_sync(qmask, comps[(2 * kk + 1) & 3], qlane + hb);   \
            int i11 = __shfl_sync(qmask, comps[(2 * kk + 1) & 3], qlane + hb + 1);\
            (AF)[4 * kk + 0] = *reinterpret_cast<const uint32_t*>(               \
                cbb + (size_t)i00 * 16 + cc * 4);                                \
            (AF)[4 * kk + 1] = *reinterpret_cast<const uint32_t*>(               \
                cbb + (size_t)i10 * 16 + cc * 4);                                \
            (AF)[4 * kk + 2] = *reinterpret_cast<const uint32_t*>(               \
                cbb + (size_t)i01 * 16 + cc * 4);                                \
            (AF)[4 * kk + 3] = *reinterpret_cast<const uint32_t*>(               \
                cbb + (size_t)i11 * 16 + cc * 4);                                \
        }                                                                        \
    }

    // ---- prologue: idx + gathers for it=0, idx for it=1 ----
    int4 sidx0 = __ldg(qp4);
    int4 sidx1 = __ldg(qp4 + 2);
    uint32_t af[16];
    GATHER_FRAGS(af, sidx0);

    // one barrier: B tile visible to all warps; mainloop is barrier-free
    __syncthreads();

    for (int it = 0; it < NIT; ++it) {
        // ---- prefetch next iter (A frags + idx), latency hidden by MMAs ----
        const bool more = (it + 1 < NIT);
        uint32_t afN[16];
        int4 sidxN;
        if (more) {
            GATHER_FRAGS(afN, sidx1);
            if (it + 2 < NIT) sidxN = __ldg(qp4 + (it + 2) * 2);
        }

        // ---- MMAs on static B chunk it ----
        const uint32_t Bb = sb + (uint32_t)it * 4096;
        #pragma unroll
        for (int kk = 0; kk < 4; ++kk) {
            uint32_t b00, b01, b10, b11, b20, b21, b30, b31;
            uint32_t off0 = b_base + (uint32_t)(kk * 32);
            ldmat_x4(Bb + SWZ(off0), b00, b01, b10, b11);
            uint32_t off1 = off0 + (16u << 7);   // tokens +16
            ldmat_x4(Bb + SWZ(off1), b20, b21, b30, b31);
            mma16816(c[0], af[4*kk], af[4*kk+1], af[4*kk+2], af[4*kk+3], b00, b01);
            mma16816(c[1], af[4*kk], af[4*kk+1], af[4*kk+2], af[4*kk+3], b10, b11);
            mma16816(c[2], af[4*kk], af[4*kk+1], af[4*kk+2], af[4*kk+3], b20, b21);
            mma16816(c[3], af[4*kk], af[4*kk+1], af[4*kk+2], af[4*kk+3], b30, b31);
        }

        if (more) {
            #pragma unroll
            for (int i = 0; i < 16; ++i) af[i] = afN[i];
            sidx1 = sidxN;
        }
    }
#undef GATHER_FRAGS

    // ---- epilogue: atomic-accumulate into g_z ----
    const int row0 = m0 + wid * 16 + (lid >> 2);
    const int col0 = (lid & 3) * 2;
    #pragma unroll
    for (int g = 0; g < 4; ++g) {
        int t0 = g * 8 + col0;
        atomicAdd(&g_z[(size_t)(t0    ) * OUT_F + row0    ], c[g][0]);
        atomicAdd(&g_z[(size_t)(t0 + 1) * OUT_F + row0    ], c[g][1]);
        atomicAdd(&g_z[(size_t)(t0    ) * OUT_F + row0 + 8], c[g][2]);
        atomicAdd(&g_z[(size_t)(t0 + 1) * OUT_F + row0 + 8], c[g][3]);
    }
}

// ---------------- K_out1: FWHT stage 1 (H_1024) of g_z ----------------
__global__ void __launch_bounds__(256) k_out1() {
    __shared__ float s[1024];
    int t = blockIdx.x >> 3;          // token
    int ch = blockIdx.x & 7;          // chunk
    size_t base = (size_t)t * OUT_F + ch * 1024;
    int tid = threadIdx.x;
    reinterpret_cast<float4*>(s)[tid] =
        reinterpret_cast<const float4*>(g_z + base)[tid];
    fwht1024(s, tid);
    #pragma unroll
    for (int pp = 0; pp < 4; ++pp) {
        int i = tid + pp * 256;
        g_tmp[base + i] = s[i];
    }
}

// ---------------- K_out2: FWHT stage 2 (H_8) * SV * Wscale -> out ----------------
__global__ void __launch_bounds__(256) k_out2(const float* __restrict__ SV,
                                              const float* __restrict__ Wscale,
                                              float* __restrict__ out) {
    int gid = blockIdx.x * 256 + threadIdx.x;   // 0..32767
    int t = gid >> 10;
    int i = gid & 1023;
    size_t base = (size_t)t * OUT_F + i;
    float v[8];
    #pragma unroll
    for (int c = 0; c < 8; ++c) v[c] = g_tmp[base + c * 1024];
    fwht8(v);
    const float ws = Wscale[0] * 0.011048543456039806f;   // Wscale / sqrt(8192)
    #pragma unroll
    for (int c = 0; c < 8; ++c)
        out[base + c * 1024] = v[c] * ws * SV[i + c * 1024];
}

// ---------------- launch ----------------
extern "C" void kernel_launch(void* const* d_in, const int* in_sizes, int n_in,
                              void* d_out, int out_size) {
    const float* x      = (const float*)d_in[0];
    const float* cb     = (const float*)d_in[1];
    const int*   qidx   = (const int*)  d_in[2];
    const float* SU     = (const float*)d_in[3];
    const float* SV     = (const float*)d_in[4];
    const float* Wscale = (const float*)d_in[5];
    float* out = (float*)d_out;

    k_pre<<<576, 256>>>(cb, x, SU);
    k_xh2<<<NTOK * 1024 / 256, 256>>>();
    k_main<<<dim3(OUT_F / 128, KSPLIT), 256>>>(qidx);
    k_out1<<<NTOK * NCHUNK, 256>>>();
    k_out2<<<NTOK * 1024 / 256, 256>>>(SV, Wscale, out);
}